// round 16
// baseline (speedup 1.0000x reference)
#include <cuda_runtime.h>
#include <cuda_bf16.h>
#include <cstdint>

#define BB 16
#define NN 4096
#define SS 1024
#define KK 32
#define DD 64
#define ROWS (BB*SS*KK)        // 524288
#define XYZ_OUT (BB*SS*3)      // 49152
#define INV_ROWS (1.0f/524288.0f)

// ---------------- scratch ----------------
__device__ float g_x0[(size_t)ROWS*64];
__device__ float g_x1[(size_t)ROWS*64];
__device__ float g_maxv[(size_t)BB*SS*128];
__device__ float g_minv[(size_t)BB*SS*128];
__device__ int   g_knn[ROWS];
__device__ float g_newxyz[BB*SS*3];
__device__ float g_stats[512];
__device__ float g_sb[512];
__device__ unsigned g_cnt[4];   // zero-init; each layer's last block resets its slot

// ---------------- bf16 helpers ----------------
__device__ __forceinline__ void split2(float v0, float v1, uint32_t& hi, uint32_t& lo) {
    __nv_bfloat16 h0 = __float2bfloat16(v0), h1 = __float2bfloat16(v1);
    __nv_bfloat16 l0 = __float2bfloat16(v0 - __bfloat162float(h0));
    __nv_bfloat16 l1 = __float2bfloat16(v1 - __bfloat162float(h1));
    hi = (uint32_t)__bfloat16_as_ushort(h0) | ((uint32_t)__bfloat16_as_ushort(h1) << 16);
    lo = (uint32_t)__bfloat16_as_ushort(l0) | ((uint32_t)__bfloat16_as_ushort(l1) << 16);
}
__device__ __forceinline__ void mma_bf16(float& d0, float& d1, float& d2, float& d3,
    uint32_t a0, uint32_t a1, uint32_t a2, uint32_t a3, uint32_t b0, uint32_t b1)
{
    asm volatile("mma.sync.aligned.m16n8k16.row.col.f32.bf16.bf16.f32 "
        "{%0,%1,%2,%3},{%4,%5,%6,%7},{%8,%9},{%0,%1,%2,%3};"
        : "+f"(d0), "+f"(d1), "+f"(d2), "+f"(d3)
        : "r"(a0), "r"(a1), "r"(a2), "r"(a3), "r"(b0), "r"(b1));
}

// ---------------- KNN: point-major, 8 register-resident query sets per warp ----------------
__global__ void knn_kernel(const float* __restrict__ xyz, const int* __restrict__ fps,
                           int* __restrict__ knn, float* __restrict__ newxyz,
                           float* __restrict__ out, float* __restrict__ stats)
{
    extern __shared__ float4 sm4[];
    if (blockIdx.x == 0 && blockIdx.y == 0) {
        for (int i = threadIdx.x; i < 512; i += blockDim.x) stats[i] = 0.0f;
    }
    int b = blockIdx.x;
    const float* xb = xyz + (size_t)b*NN*3;
    for (int i = threadIdx.x; i < NN; i += blockDim.x) {
        float x = xb[3*i], y = xb[3*i+1], z = xb[3*i+2];
        sm4[i] = make_float4(x, y, z, x*x + y*y + z*z);
    }
    __syncthreads();
    int warp = threadIdx.x >> 5, lane = threadIdx.x & 31;
    const unsigned F = 0xffffffffu;

    float qx[8], qy[8], qz[8], qq[8], dres[8], thr[8];
    int myi[8], amax[8];
    int sbase = blockIdx.y*64 + warp*8;

    #pragma unroll
    for (int q = 0; q < 8; ++q) {
        int n0 = fps[b*SS + sbase + q];
        float4 v = sm4[n0];
        qx[q] = v.x; qy[q] = v.y; qz[q] = v.z; qq[q] = v.w;
    }
    {
        float4 p = sm4[lane];
        #pragma unroll
        for (int q = 0; q < 8; ++q) {
            float dc = fmaxf(fmaf(-2.0f, fmaf(qx[q], p.x, fmaf(qy[q], p.y, qz[q]*p.z)), qq[q]) + p.w, 0.0f);
            dres[q] = dc; myi[q] = lane;
            int im = __reduce_max_sync(F, __float_as_int(dc));
            thr[q] = __int_as_float(im);
            amax[q] = __ffs(__ballot_sync(F, __float_as_int(dc) == im)) - 1;
        }
    }
    for (int base = 32; base < NN; base += 32) {
        float4 p = sm4[base + lane];
        #pragma unroll
        for (int q = 0; q < 8; ++q) {
            float dc = fmaxf(fmaf(-2.0f, fmaf(qx[q], p.x, fmaf(qy[q], p.y, qz[q]*p.z)), qq[q]) + p.w, 0.0f);
            unsigned m = __ballot_sync(F, dc < thr[q]);
            while (m) {
                int src = __ffs(m) - 1; m &= m - 1;
                float dcand = __shfl_sync(F, dc, src);
                if (dcand < thr[q]) {
                    if (lane == amax[q]) { dres[q] = dcand; myi[q] = base + src; }
                    int db = __float_as_int(dres[q]);
                    int im = __reduce_max_sync(F, db);
                    thr[q] = __int_as_float(im);
                    amax[q] = __ffs(__ballot_sync(F, db == im)) - 1;
                }
            }
        }
    }
    #pragma unroll
    for (int q = 0; q < 8; ++q) {
        int s = sbase + q;
        knn[((size_t)b*SS + s)*KK + lane] = myi[q];
        if (lane == 0) {
            size_t o = ((size_t)b*SS + s)*3;
            newxyz[o] = qx[q]; newxyz[o+1] = qy[q]; newxyz[o+2] = qz[q];
            out[o] = qx[q]; out[o+1] = qy[q]; out[o+2] = qz[q];
        }
    }
}

// ---------------- shared MMA compute (bf16x3, 2 m-tiles per warp) ----------------
// Each warp owns 32 out-channels (2 m-tiles) -> each B fragment load feeds 6 MMAs,
// halving smem read traffic vs 1 m-tile per warp.
template<int COUT, int K_REAL, int NK, int STRIDE, bool MAXMIN>
__device__ __forceinline__ void mma_compute_bf16(
    const uint32_t* __restrict__ sHi, const uint32_t* __restrict__ sLo,
    const float* __restrict__ W, const float* __restrict__ bconv,
    float* __restrict__ xout, size_t rowBase, float* sS, float* sQ,
    float* __restrict__ gmax, float* __restrict__ gmin)
{
    constexpr int CG      = COUT/32;      // channel groups of 32
    constexpr int RH      = 8/CG;         // row-halves
    constexpr int ROWS_PW = 128/RH;       // rows per warp
    constexpr int NG      = ROWS_PW/8;
    int warp = threadIdx.x >> 5, lane = threadIdx.x & 31;
    int g = lane >> 2, t = lane & 3;
    int cg = warp % CG, rh = warp / CG;
    int mb0 = cg * 32;
    int rowOff = rh * ROWS_PW;

    uint32_t ahi[2][NK][4], alo[2][NK][4];
    #pragma unroll
    for (int mt = 0; mt < 2; ++mt) {
        #pragma unroll
        for (int ks = 0; ks < NK; ++ks) {
            #pragma unroll
            for (int j = 0; j < 4; ++j) {
                int r = mb0 + mt*16 + g + (j & 1) * 8;
                int c0 = ks*16 + 2*t + (j >> 1) * 8;
                float v0 = (c0     < K_REAL) ? W[r*K_REAL + c0]     : 0.0f;
                float v1 = (c0 + 1 < K_REAL) ? W[r*K_REAL + c0 + 1] : 0.0f;
                split2(v0, v1, ahi[mt][ks][j], alo[mt][ks][j]);
            }
        }
    }
    float bias[2][2];
    #pragma unroll
    for (int mt = 0; mt < 2; ++mt) {
        bias[mt][0] = bconv[mb0 + mt*16 + g];
        bias[mt][1] = bconv[mb0 + mt*16 + 8 + g];
    }
    float st_s[2][2] = {{0,0},{0,0}}, st_q[2][2] = {{0,0},{0,0}};
    float mx[2][2] = {{-3.4e38f,-3.4e38f},{-3.4e38f,-3.4e38f}};
    float mn[2][2] = {{ 3.4e38f, 3.4e38f},{ 3.4e38f, 3.4e38f}};

    #pragma unroll 1
    for (int ng = 0; ng < NG; ++ng) {
        int nb = rowOff + ng*8;
        float d[2][4], e[2][4], f[2][4];
        #pragma unroll
        for (int mt = 0; mt < 2; ++mt) {
            d[mt][0] = bias[mt][0]; d[mt][1] = bias[mt][0];
            d[mt][2] = bias[mt][1]; d[mt][3] = bias[mt][1];
            #pragma unroll
            for (int j = 0; j < 4; ++j) { e[mt][j] = 0.0f; f[mt][j] = 0.0f; }
        }
        const uint32_t* bh = sHi + (nb + g)*STRIDE + t;
        const uint32_t* bl = sLo + (nb + g)*STRIDE + t;
        #pragma unroll
        for (int ks = 0; ks < NK; ++ks) {
            uint32_t b0h = bh[ks*8];
            uint32_t b1h = bh[ks*8 + 4];
            uint32_t b0l = bl[ks*8];
            uint32_t b1l = bl[ks*8 + 4];
            #pragma unroll
            for (int mt = 0; mt < 2; ++mt) {
                mma_bf16(d[mt][0],d[mt][1],d[mt][2],d[mt][3],
                         ahi[mt][ks][0],ahi[mt][ks][1],ahi[mt][ks][2],ahi[mt][ks][3], b0h,b1h);
                mma_bf16(e[mt][0],e[mt][1],e[mt][2],e[mt][3],
                         ahi[mt][ks][0],ahi[mt][ks][1],ahi[mt][ks][2],ahi[mt][ks][3], b0l,b1l);
                mma_bf16(f[mt][0],f[mt][1],f[mt][2],f[mt][3],
                         alo[mt][ks][0],alo[mt][ks][1],alo[mt][ks][2],alo[mt][ks][3], b0h,b1h);
            }
        }
        #pragma unroll
        for (int mt = 0; mt < 2; ++mt) {
            #pragma unroll
            for (int j = 0; j < 4; ++j) d[mt][j] += e[mt][j] + f[mt][j];

            if constexpr (!MAXMIN) {
                float* p = xout + (rowBase + nb + 2*t)*COUT + mb0 + mt*16 + g;
                p[0] = d[mt][0]; p[COUT] = d[mt][1]; p[8] = d[mt][2]; p[COUT + 8] = d[mt][3];
            }
            st_s[mt][0] += d[mt][0] + d[mt][1];
            st_q[mt][0] += d[mt][0]*d[mt][0] + d[mt][1]*d[mt][1];
            st_s[mt][1] += d[mt][2] + d[mt][3];
            st_q[mt][1] += d[mt][2]*d[mt][2] + d[mt][3]*d[mt][3];
            if constexpr (MAXMIN) {
                mx[mt][0] = fmaxf(mx[mt][0], fmaxf(d[mt][0], d[mt][1]));
                mn[mt][0] = fminf(mn[mt][0], fminf(d[mt][0], d[mt][1]));
                mx[mt][1] = fmaxf(mx[mt][1], fmaxf(d[mt][2], d[mt][3]));
                mn[mt][1] = fminf(mn[mt][1], fminf(d[mt][2], d[mt][3]));
            }
        }
        if constexpr (MAXMIN) {
            if ((ng & 3) == 3) {
                #pragma unroll
                for (int mt = 0; mt < 2; ++mt) {
                    #pragma unroll
                    for (int h = 0; h < 2; ++h) {
                        #pragma unroll
                        for (int off = 1; off < 4; off <<= 1) {
                            mx[mt][h] = fmaxf(mx[mt][h], __shfl_xor_sync(0xffffffffu, mx[mt][h], off));
                            mn[mt][h] = fminf(mn[mt][h], __shfl_xor_sync(0xffffffffu, mn[mt][h], off));
                        }
                    }
                }
                if (t == 0) {
                    int bs = (int)((rowBase + rowOff) >> 5) + (ng >> 2);
                    #pragma unroll
                    for (int mt = 0; mt < 2; ++mt) {
                        gmax[bs*128 + mb0 + mt*16 + g]     = mx[mt][0];
                        gmin[bs*128 + mb0 + mt*16 + g]     = mn[mt][0];
                        gmax[bs*128 + mb0 + mt*16 + 8 + g] = mx[mt][1];
                        gmin[bs*128 + mb0 + mt*16 + 8 + g] = mn[mt][1];
                    }
                }
                #pragma unroll
                for (int mt = 0; mt < 2; ++mt) {
                    mx[mt][0] = mx[mt][1] = -3.4e38f;
                    mn[mt][0] = mn[mt][1] = 3.4e38f;
                }
            }
        }
    }
    #pragma unroll
    for (int mt = 0; mt < 2; ++mt) {
        #pragma unroll
        for (int h = 0; h < 2; ++h) {
            #pragma unroll
            for (int off = 1; off < 4; off <<= 1) {
                st_s[mt][h] += __shfl_xor_sync(0xffffffffu, st_s[mt][h], off);
                st_q[mt][h] += __shfl_xor_sync(0xffffffffu, st_q[mt][h], off);
            }
        }
    }
    if (t == 0) {
        #pragma unroll
        for (int mt = 0; mt < 2; ++mt) {
            atomicAdd(&sS[mb0 + mt*16 + g], st_s[mt][0]);
            atomicAdd(&sQ[mb0 + mt*16 + g], st_q[mt][0]);
            atomicAdd(&sS[mb0 + mt*16 + 8 + g], st_s[mt][1]);
            atomicAdd(&sQ[mb0 + mt*16 + 8 + g], st_q[mt][1]);
        }
    }
}

// ---------------- in-kernel BN finalize (last block) ----------------
template<int COUT>
__device__ __forceinline__ void tail_finalize(
    float* statS, float* statQ, const float* __restrict__ gamma,
    const float* __restrict__ beta, float* __restrict__ sb, unsigned* cnt)
{
    __shared__ bool isLast;
    int tid = threadIdx.x;
    __threadfence();
    if (tid == 0) isLast = (atomicAdd(cnt, 1u) == gridDim.x - 1);
    __syncthreads();
    if (isLast) {
        if (tid == 0) *cnt = 0;
        if (tid < COUT) {
            volatile float* vs = statS;
            volatile float* vq = statQ;
            float mean = vs[tid] * INV_ROWS;
            float var  = vq[tid] * INV_ROWS - mean*mean;
            float sc   = gamma[tid] * rsqrtf(var + 1e-5f);
            sb[tid]        = sc;
            sb[COUT + tid] = beta[tid] - mean*sc;
        }
    }
}

// ---------------- Layer 0: gather + concat + 67->64 ----------------
__global__ __launch_bounds__(256) void layer0_mma(
    const float* __restrict__ xyz, const float* __restrict__ points,
    const int* __restrict__ knn, const float* __restrict__ newxyz,
    const float* __restrict__ W, const float* __restrict__ bconv,
    float* __restrict__ xout, float* __restrict__ statS, float* __restrict__ statQ,
    const float* __restrict__ gamma, const float* __restrict__ beta,
    float* __restrict__ sb, unsigned* cnt)
{
    extern __shared__ char smraw[];
    __nv_bfloat16* sHi = (__nv_bfloat16*)smraw;         // 128*88
    __nv_bfloat16* sLo = sHi + 128*88;
    float* sS = (float*)(sLo + 128*88);
    float* sQ = sS + 64;
    int tid = threadIdx.x;
    size_t rowBase = (size_t)blockIdx.x * 128;
    if (tid < 64) { sS[tid] = 0.0f; sQ[tid] = 0.0f; }

    {
        int r = tid >> 1, half = tid & 1;
        size_t row = rowBase + r;
        int b = (int)(row >> 15);
        int s = (int)((row >> 5) & 1023);
        int n = knn[row];
        const float4* prow = (const float4*)(points + ((size_t)b*NN + n)*DD);
        __nv_bfloat16* dh = sHi + r*88;
        __nv_bfloat16* dl = sLo + r*88;
        auto put = [&](int c, float v) {
            __nv_bfloat16 h = __float2bfloat16(v);
            dh[c] = h;
            dl[c] = __float2bfloat16(v - __bfloat162float(h));
        };
        if (half == 0) {
            size_t xo = ((size_t)b*NN + n)*3;
            size_t qo = ((size_t)b*SS + s)*3;
            put(0, xyz[xo]   - newxyz[qo]);
            put(1, xyz[xo+1] - newxyz[qo+1]);
            put(2, xyz[xo+2] - newxyz[qo+2]);
            #pragma unroll
            for (int j = 0; j < 8; ++j) {
                float4 v = prow[j];
                put(3+4*j, v.x); put(4+4*j, v.y); put(5+4*j, v.z); put(6+4*j, v.w);
            }
        } else {
            #pragma unroll
            for (int j = 8; j < 16; ++j) {
                float4 v = prow[j];
                put(3+4*j, v.x); put(4+4*j, v.y); put(5+4*j, v.z); put(6+4*j, v.w);
            }
            #pragma unroll
            for (int c = 67; c < 80; ++c) {
                dh[c] = __ushort_as_bfloat16(0); dl[c] = __ushort_as_bfloat16(0);
            }
        }
    }
    __syncthreads();
    mma_compute_bf16<64, 67, 5, 44, false>((const uint32_t*)sHi, (const uint32_t*)sLo,
        W, bconv, xout, rowBase, sS, sQ, nullptr, nullptr);
    __syncthreads();
    if (tid < 64) { atomicAdd(&statS[tid], sS[tid]); atomicAdd(&statQ[tid], sQ[tid]); }
    tail_finalize<64>(statS, statQ, gamma, beta, sb, cnt);
}

// ---------------- Layers 1/2: BN+ReLU fused on load ----------------
template<int COUT, bool MAXMIN>
__global__ __launch_bounds__(256) void layer12_mma(
    const float* __restrict__ xin, float* __restrict__ xout,
    const float* __restrict__ W, const float* __restrict__ bconv,
    const float* __restrict__ sbin,
    float* __restrict__ statS, float* __restrict__ statQ,
    float* __restrict__ gmax, float* __restrict__ gmin,
    const float* __restrict__ gamma, const float* __restrict__ beta,
    float* __restrict__ sb, unsigned* cnt)
{
    extern __shared__ char smraw[];
    uint32_t* sHi = (uint32_t*)smraw;       // 128*36
    uint32_t* sLo = sHi + 128*36;
    float* sS  = (float*)(sLo + 128*36);    // COUT
    float* sQ  = sS + COUT;
    float* sci = sQ + COUT;                 // 128
    int tid = threadIdx.x;
    size_t rowBase = (size_t)blockIdx.x * 128;

    if (tid < 128) sci[tid] = sbin[tid];
    for (int e = tid; e < COUT; e += 256) { sS[e] = 0.0f; sQ[e] = 0.0f; }
    __syncthreads();

    const float4* src = (const float4*)(xin + rowBase*64);
    #pragma unroll
    for (int k = 0; k < 8; ++k) {
        int e4 = tid + k*256;
        float4 v = src[e4];
        int lin = e4*4; int r = lin >> 6; int c = lin & 63;
        float y0 = fmaxf(fmaf(v.x, sci[c+0], sci[64+c+0]), 0.0f);
        float y1 = fmaxf(fmaf(v.y, sci[c+1], sci[64+c+1]), 0.0f);
        float y2 = fmaxf(fmaf(v.z, sci[c+2], sci[64+c+2]), 0.0f);
        float y3 = fmaxf(fmaf(v.w, sci[c+3], sci[64+c+3]), 0.0f);
        uint2 hv, lv;
        split2(y0, y1, hv.x, lv.x);
        split2(y2, y3, hv.y, lv.y);
        int off = r*36 + (c >> 1);
        *(uint2*)(sHi + off) = hv;
        *(uint2*)(sLo + off) = lv;
    }
    __syncthreads();
    mma_compute_bf16<COUT, 64, 4, 36, MAXMIN>(sHi, sLo, W, bconv, xout, rowBase,
        sS, sQ, gmax, gmin);
    __syncthreads();
    if (tid < COUT) { atomicAdd(&statS[tid], sS[tid]); atomicAdd(&statQ[tid], sQ[tid]); }
    tail_finalize<COUT>(statS, statQ, gamma, beta, sb, cnt);
}

// ---------------- final: BN+ReLU applied to max/min over K ----------------
__global__ void final_max_kernel(const float* __restrict__ gmax, const float* __restrict__ gmin,
                                 const float* __restrict__ sb, float* __restrict__ out)
{
    int i = blockIdx.x*256 + threadIdx.x;
    int ch = i & 127;
    float sc = sb[ch], bi = sb[128 + ch];
    float v = (sc >= 0.0f) ? gmax[i] : gmin[i];
    out[XYZ_OUT + i] = fmaxf(fmaf(v, sc, bi), 0.0f);
}

// ---------------- launch ----------------
extern "C" void kernel_launch(void* const* d_in, const int* in_sizes, int n_in,
                              void* d_out, int out_size)
{
    const float* xyz    = (const float*)d_in[0];
    const float* points = (const float*)d_in[1];
    const int*   fps    = (const int*)d_in[2];
    const float* w0  = (const float*)d_in[3];
    const float* b0  = (const float*)d_in[4];
    const float* g0  = (const float*)d_in[5];
    const float* be0 = (const float*)d_in[6];
    const float* w1  = (const float*)d_in[7];
    const float* b1  = (const float*)d_in[8];
    const float* g1  = (const float*)d_in[9];
    const float* be1 = (const float*)d_in[10];
    const float* w2  = (const float*)d_in[11];
    const float* b2  = (const float*)d_in[12];
    const float* g2  = (const float*)d_in[13];
    const float* be2 = (const float*)d_in[14];
    float* out = (float*)d_out;

    float *px0, *px1, *pmx, *pmn, *pnx, *pst, *psb;
    int* pknn;
    unsigned* pcnt;
    cudaGetSymbolAddress((void**)&px0,  g_x0);
    cudaGetSymbolAddress((void**)&px1,  g_x1);
    cudaGetSymbolAddress((void**)&pmx,  g_maxv);
    cudaGetSymbolAddress((void**)&pmn,  g_minv);
    cudaGetSymbolAddress((void**)&pnx,  g_newxyz);
    cudaGetSymbolAddress((void**)&pst,  g_stats);
    cudaGetSymbolAddress((void**)&psb,  g_sb);
    cudaGetSymbolAddress((void**)&pknn, g_knn);
    cudaGetSymbolAddress((void**)&pcnt, g_cnt);

    const int SM_KNN = NN*16;                          // 65536
    const int SM0 = 128*88*2*2 + 2*64*4;               // 45568
    const int SM1 = 128*36*4*2 + (2*64 + 128)*4;       // 37888
    const int SM2 = 128*36*4*2 + (2*128 + 128)*4;      // 38400

    cudaFuncSetAttribute(knn_kernel, cudaFuncAttributeMaxDynamicSharedMemorySize, SM_KNN);
    cudaFuncSetAttribute(layer0_mma, cudaFuncAttributeMaxDynamicSharedMemorySize, SM0);
    cudaFuncSetAttribute(layer12_mma<64,false>,  cudaFuncAttributeMaxDynamicSharedMemorySize, SM1);
    cudaFuncSetAttribute(layer12_mma<128,true>, cudaFuncAttributeMaxDynamicSharedMemorySize, SM2);

    knn_kernel<<<dim3(BB, 16), 256, SM_KNN>>>(xyz, fps, pknn, pnx, out, pst);
    layer0_mma<<<ROWS/128, 256, SM0>>>(xyz, points, pknn, pnx, w0, b0, px0,
        pst, pst + 64, g0, be0, psb, pcnt);
    layer12_mma<64,false><<<ROWS/128, 256, SM1>>>(px0, px1, w1, b1, psb,
        pst + 128, pst + 192, nullptr, nullptr, g1, be1, psb + 128, pcnt + 1);
    layer12_mma<128,true><<<ROWS/128, 256, SM2>>>(px1, nullptr, w2, b2, psb + 128,
        pst + 256, pst + 384, pmx, pmn, g2, be2, psb + 256, pcnt + 2);
    final_max_kernel<<<BB*SS*128/256, 256>>>(pmx, pmn, psb + 256, out);
}

// round 17
// speedup vs baseline: 1.0016x; 1.0016x over previous
#include <cuda_runtime.h>
#include <cuda_bf16.h>
#include <cstdint>

#define BB 16
#define NN 4096
#define SS 1024
#define KK 32
#define DD 64
#define ROWS (BB*SS*KK)        // 524288
#define XYZ_OUT (BB*SS*3)      // 49152
#define INV_ROWS (1.0f/524288.0f)

// ---------------- scratch ----------------
__device__ float g_x0[(size_t)ROWS*64];
__device__ float g_x1[(size_t)ROWS*64];
__device__ float g_maxv[(size_t)BB*SS*128];
__device__ float g_minv[(size_t)BB*SS*128];
__device__ int   g_knn[ROWS];
__device__ float g_newxyz[BB*SS*3];
__device__ float g_stats[512];
__device__ float g_sb[512];
__device__ unsigned g_cnt[4];   // zero-init; each layer's last block resets its slot

// ---------------- bf16 helpers ----------------
__device__ __forceinline__ void split2(float v0, float v1, uint32_t& hi, uint32_t& lo) {
    __nv_bfloat16 h0 = __float2bfloat16(v0), h1 = __float2bfloat16(v1);
    __nv_bfloat16 l0 = __float2bfloat16(v0 - __bfloat162float(h0));
    __nv_bfloat16 l1 = __float2bfloat16(v1 - __bfloat162float(h1));
    hi = (uint32_t)__bfloat16_as_ushort(h0) | ((uint32_t)__bfloat16_as_ushort(h1) << 16);
    lo = (uint32_t)__bfloat16_as_ushort(l0) | ((uint32_t)__bfloat16_as_ushort(l1) << 16);
}
__device__ __forceinline__ void mma_bf16(float& d0, float& d1, float& d2, float& d3,
    uint32_t a0, uint32_t a1, uint32_t a2, uint32_t a3, uint32_t b0, uint32_t b1)
{
    asm volatile("mma.sync.aligned.m16n8k16.row.col.f32.bf16.bf16.f32 "
        "{%0,%1,%2,%3},{%4,%5,%6,%7},{%8,%9},{%0,%1,%2,%3};"
        : "+f"(d0), "+f"(d1), "+f"(d2), "+f"(d3)
        : "r"(a0), "r"(a1), "r"(a2), "r"(a3), "r"(b0), "r"(b1));
}

// ---------------- KNN: point-major, 8 register-resident query sets per warp ----------------
__global__ void knn_kernel(const float* __restrict__ xyz, const int* __restrict__ fps,
                           int* __restrict__ knn, float* __restrict__ newxyz,
                           float* __restrict__ out, float* __restrict__ stats)
{
    extern __shared__ float4 sm4[];
    if (blockIdx.x == 0 && blockIdx.y == 0) {
        for (int i = threadIdx.x; i < 512; i += blockDim.x) stats[i] = 0.0f;
    }
    int b = blockIdx.x;
    const float* xb = xyz + (size_t)b*NN*3;
    for (int i = threadIdx.x; i < NN; i += blockDim.x) {
        float x = xb[3*i], y = xb[3*i+1], z = xb[3*i+2];
        sm4[i] = make_float4(x, y, z, x*x + y*y + z*z);
    }
    __syncthreads();
    int warp = threadIdx.x >> 5, lane = threadIdx.x & 31;
    const unsigned F = 0xffffffffu;

    float qx[8], qy[8], qz[8], qq[8], dres[8], thr[8];
    int myi[8], amax[8];
    int sbase = blockIdx.y*64 + warp*8;

    #pragma unroll
    for (int q = 0; q < 8; ++q) {
        int n0 = fps[b*SS + sbase + q];
        float4 v = sm4[n0];
        qx[q] = v.x; qy[q] = v.y; qz[q] = v.z; qq[q] = v.w;
    }
    {
        float4 p = sm4[lane];
        #pragma unroll
        for (int q = 0; q < 8; ++q) {
            float dc = fmaxf(fmaf(-2.0f, fmaf(qx[q], p.x, fmaf(qy[q], p.y, qz[q]*p.z)), qq[q]) + p.w, 0.0f);
            dres[q] = dc; myi[q] = lane;
            int im = __reduce_max_sync(F, __float_as_int(dc));
            thr[q] = __int_as_float(im);
            amax[q] = __ffs(__ballot_sync(F, __float_as_int(dc) == im)) - 1;
        }
    }
    for (int base = 32; base < NN; base += 32) {
        float4 p = sm4[base + lane];
        #pragma unroll
        for (int q = 0; q < 8; ++q) {
            float dc = fmaxf(fmaf(-2.0f, fmaf(qx[q], p.x, fmaf(qy[q], p.y, qz[q]*p.z)), qq[q]) + p.w, 0.0f);
            unsigned m = __ballot_sync(F, dc < thr[q]);
            while (m) {
                int src = __ffs(m) - 1; m &= m - 1;
                float dcand = __shfl_sync(F, dc, src);
                if (dcand < thr[q]) {
                    if (lane == amax[q]) { dres[q] = dcand; myi[q] = base + src; }
                    int db = __float_as_int(dres[q]);
                    int im = __reduce_max_sync(F, db);
                    thr[q] = __int_as_float(im);
                    amax[q] = __ffs(__ballot_sync(F, db == im)) - 1;
                }
            }
        }
    }
    #pragma unroll
    for (int q = 0; q < 8; ++q) {
        int s = sbase + q;
        knn[((size_t)b*SS + s)*KK + lane] = myi[q];
        if (lane == 0) {
            size_t o = ((size_t)b*SS + s)*3;
            newxyz[o] = qx[q]; newxyz[o+1] = qy[q]; newxyz[o+2] = qz[q];
            out[o] = qx[q]; out[o+1] = qy[q]; out[o+2] = qz[q];
        }
    }
}

// ---------------- shared MMA compute (bf16x3, 2 m-tiles per warp) ----------------
// Each warp owns 32 out-channels (2 m-tiles) -> each B fragment load feeds 6 MMAs,
// halving smem read traffic vs 1 m-tile per warp.
template<int COUT, int K_REAL, int NK, int STRIDE, bool MAXMIN>
__device__ __forceinline__ void mma_compute_bf16(
    const uint32_t* __restrict__ sHi, const uint32_t* __restrict__ sLo,
    const float* __restrict__ W, const float* __restrict__ bconv,
    float* __restrict__ xout, size_t rowBase, float* sS, float* sQ,
    float* __restrict__ gmax, float* __restrict__ gmin)
{
    constexpr int CG      = COUT/32;      // channel groups of 32
    constexpr int RH      = 8/CG;         // row-halves
    constexpr int ROWS_PW = 128/RH;       // rows per warp
    constexpr int NG      = ROWS_PW/8;
    int warp = threadIdx.x >> 5, lane = threadIdx.x & 31;
    int g = lane >> 2, t = lane & 3;
    int cg = warp % CG, rh = warp / CG;
    int mb0 = cg * 32;
    int rowOff = rh * ROWS_PW;

    uint32_t ahi[2][NK][4], alo[2][NK][4];
    #pragma unroll
    for (int mt = 0; mt < 2; ++mt) {
        #pragma unroll
        for (int ks = 0; ks < NK; ++ks) {
            #pragma unroll
            for (int j = 0; j < 4; ++j) {
                int r = mb0 + mt*16 + g + (j & 1) * 8;
                int c0 = ks*16 + 2*t + (j >> 1) * 8;
                float v0 = (c0     < K_REAL) ? W[r*K_REAL + c0]     : 0.0f;
                float v1 = (c0 + 1 < K_REAL) ? W[r*K_REAL + c0 + 1] : 0.0f;
                split2(v0, v1, ahi[mt][ks][j], alo[mt][ks][j]);
            }
        }
    }
    float bias[2][2];
    #pragma unroll
    for (int mt = 0; mt < 2; ++mt) {
        bias[mt][0] = bconv[mb0 + mt*16 + g];
        bias[mt][1] = bconv[mb0 + mt*16 + 8 + g];
    }
    float st_s[2][2] = {{0,0},{0,0}}, st_q[2][2] = {{0,0},{0,0}};
    float mx[2][2] = {{-3.4e38f,-3.4e38f},{-3.4e38f,-3.4e38f}};
    float mn[2][2] = {{ 3.4e38f, 3.4e38f},{ 3.4e38f, 3.4e38f}};

    #pragma unroll 1
    for (int ng = 0; ng < NG; ++ng) {
        int nb = rowOff + ng*8;
        float d[2][4], e[2][4], f[2][4];
        #pragma unroll
        for (int mt = 0; mt < 2; ++mt) {
            d[mt][0] = bias[mt][0]; d[mt][1] = bias[mt][0];
            d[mt][2] = bias[mt][1]; d[mt][3] = bias[mt][1];
            #pragma unroll
            for (int j = 0; j < 4; ++j) { e[mt][j] = 0.0f; f[mt][j] = 0.0f; }
        }
        const uint32_t* bh = sHi + (nb + g)*STRIDE + t;
        const uint32_t* bl = sLo + (nb + g)*STRIDE + t;
        #pragma unroll
        for (int ks = 0; ks < NK; ++ks) {
            uint32_t b0h = bh[ks*8];
            uint32_t b1h = bh[ks*8 + 4];
            uint32_t b0l = bl[ks*8];
            uint32_t b1l = bl[ks*8 + 4];
            #pragma unroll
            for (int mt = 0; mt < 2; ++mt) {
                mma_bf16(d[mt][0],d[mt][1],d[mt][2],d[mt][3],
                         ahi[mt][ks][0],ahi[mt][ks][1],ahi[mt][ks][2],ahi[mt][ks][3], b0h,b1h);
                mma_bf16(e[mt][0],e[mt][1],e[mt][2],e[mt][3],
                         ahi[mt][ks][0],ahi[mt][ks][1],ahi[mt][ks][2],ahi[mt][ks][3], b0l,b1l);
                mma_bf16(f[mt][0],f[mt][1],f[mt][2],f[mt][3],
                         alo[mt][ks][0],alo[mt][ks][1],alo[mt][ks][2],alo[mt][ks][3], b0h,b1h);
            }
        }
        #pragma unroll
        for (int mt = 0; mt < 2; ++mt) {
            #pragma unroll
            for (int j = 0; j < 4; ++j) d[mt][j] += e[mt][j] + f[mt][j];

            if constexpr (!MAXMIN) {
                float* p = xout + (rowBase + nb + 2*t)*COUT + mb0 + mt*16 + g;
                p[0] = d[mt][0]; p[COUT] = d[mt][1]; p[8] = d[mt][2]; p[COUT + 8] = d[mt][3];
            }
            st_s[mt][0] += d[mt][0] + d[mt][1];
            st_q[mt][0] += d[mt][0]*d[mt][0] + d[mt][1]*d[mt][1];
            st_s[mt][1] += d[mt][2] + d[mt][3];
            st_q[mt][1] += d[mt][2]*d[mt][2] + d[mt][3]*d[mt][3];
            if constexpr (MAXMIN) {
                mx[mt][0] = fmaxf(mx[mt][0], fmaxf(d[mt][0], d[mt][1]));
                mn[mt][0] = fminf(mn[mt][0], fminf(d[mt][0], d[mt][1]));
                mx[mt][1] = fmaxf(mx[mt][1], fmaxf(d[mt][2], d[mt][3]));
                mn[mt][1] = fminf(mn[mt][1], fminf(d[mt][2], d[mt][3]));
            }
        }
        if constexpr (MAXMIN) {
            if ((ng & 3) == 3) {
                #pragma unroll
                for (int mt = 0; mt < 2; ++mt) {
                    #pragma unroll
                    for (int h = 0; h < 2; ++h) {
                        #pragma unroll
                        for (int off = 1; off < 4; off <<= 1) {
                            mx[mt][h] = fmaxf(mx[mt][h], __shfl_xor_sync(0xffffffffu, mx[mt][h], off));
                            mn[mt][h] = fminf(mn[mt][h], __shfl_xor_sync(0xffffffffu, mn[mt][h], off));
                        }
                    }
                }
                if (t == 0) {
                    int bs = (int)((rowBase + rowOff) >> 5) + (ng >> 2);
                    #pragma unroll
                    for (int mt = 0; mt < 2; ++mt) {
                        gmax[bs*128 + mb0 + mt*16 + g]     = mx[mt][0];
                        gmin[bs*128 + mb0 + mt*16 + g]     = mn[mt][0];
                        gmax[bs*128 + mb0 + mt*16 + 8 + g] = mx[mt][1];
                        gmin[bs*128 + mb0 + mt*16 + 8 + g] = mn[mt][1];
                    }
                }
                #pragma unroll
                for (int mt = 0; mt < 2; ++mt) {
                    mx[mt][0] = mx[mt][1] = -3.4e38f;
                    mn[mt][0] = mn[mt][1] = 3.4e38f;
                }
            }
        }
    }
    #pragma unroll
    for (int mt = 0; mt < 2; ++mt) {
        #pragma unroll
        for (int h = 0; h < 2; ++h) {
            #pragma unroll
            for (int off = 1; off < 4; off <<= 1) {
                st_s[mt][h] += __shfl_xor_sync(0xffffffffu, st_s[mt][h], off);
                st_q[mt][h] += __shfl_xor_sync(0xffffffffu, st_q[mt][h], off);
            }
        }
    }
    if (t == 0) {
        #pragma unroll
        for (int mt = 0; mt < 2; ++mt) {
            atomicAdd(&sS[mb0 + mt*16 + g], st_s[mt][0]);
            atomicAdd(&sQ[mb0 + mt*16 + g], st_q[mt][0]);
            atomicAdd(&sS[mb0 + mt*16 + 8 + g], st_s[mt][1]);
            atomicAdd(&sQ[mb0 + mt*16 + 8 + g], st_q[mt][1]);
        }
    }
}

// ---------------- in-kernel BN finalize (last block) ----------------
template<int COUT>
__device__ __forceinline__ void tail_finalize(
    float* statS, float* statQ, const float* __restrict__ gamma,
    const float* __restrict__ beta, float* __restrict__ sb, unsigned* cnt)
{
    __shared__ bool isLast;
    int tid = threadIdx.x;
    __threadfence();
    if (tid == 0) isLast = (atomicAdd(cnt, 1u) == gridDim.x - 1);
    __syncthreads();
    if (isLast) {
        if (tid == 0) *cnt = 0;
        if (tid < COUT) {
            volatile float* vs = statS;
            volatile float* vq = statQ;
            float mean = vs[tid] * INV_ROWS;
            float var  = vq[tid] * INV_ROWS - mean*mean;
            float sc   = gamma[tid] * rsqrtf(var + 1e-5f);
            sb[tid]        = sc;
            sb[COUT + tid] = beta[tid] - mean*sc;
        }
    }
}

// ---------------- Layer 0: gather + concat + 67->64 ----------------
__global__ __launch_bounds__(256) void layer0_mma(
    const float* __restrict__ xyz, const float* __restrict__ points,
    const int* __restrict__ knn, const float* __restrict__ newxyz,
    const float* __restrict__ W, const float* __restrict__ bconv,
    float* __restrict__ xout, float* __restrict__ statS, float* __restrict__ statQ,
    const float* __restrict__ gamma, const float* __restrict__ beta,
    float* __restrict__ sb, unsigned* cnt)
{
    extern __shared__ char smraw[];
    __nv_bfloat16* sHi = (__nv_bfloat16*)smraw;         // 128*88
    __nv_bfloat16* sLo = sHi + 128*88;
    float* sS = (float*)(sLo + 128*88);
    float* sQ = sS + 64;
    int tid = threadIdx.x;
    size_t rowBase = (size_t)blockIdx.x * 128;
    if (tid < 64) { sS[tid] = 0.0f; sQ[tid] = 0.0f; }

    {
        int r = tid >> 1, half = tid & 1;
        size_t row = rowBase + r;
        int b = (int)(row >> 15);
        int s = (int)((row >> 5) & 1023);
        int n = knn[row];
        const float4* prow = (const float4*)(points + ((size_t)b*NN + n)*DD);
        __nv_bfloat16* dh = sHi + r*88;
        __nv_bfloat16* dl = sLo + r*88;
        auto put = [&](int c, float v) {
            __nv_bfloat16 h = __float2bfloat16(v);
            dh[c] = h;
            dl[c] = __float2bfloat16(v - __bfloat162float(h));
        };
        if (half == 0) {
            size_t xo = ((size_t)b*NN + n)*3;
            size_t qo = ((size_t)b*SS + s)*3;
            put(0, xyz[xo]   - newxyz[qo]);
            put(1, xyz[xo+1] - newxyz[qo+1]);
            put(2, xyz[xo+2] - newxyz[qo+2]);
            #pragma unroll
            for (int j = 0; j < 8; ++j) {
                float4 v = prow[j];
                put(3+4*j, v.x); put(4+4*j, v.y); put(5+4*j, v.z); put(6+4*j, v.w);
            }
        } else {
            #pragma unroll
            for (int j = 8; j < 16; ++j) {
                float4 v = prow[j];
                put(3+4*j, v.x); put(4+4*j, v.y); put(5+4*j, v.z); put(6+4*j, v.w);
            }
            #pragma unroll
            for (int c = 67; c < 80; ++c) {
                dh[c] = __ushort_as_bfloat16(0); dl[c] = __ushort_as_bfloat16(0);
            }
        }
    }
    __syncthreads();
    mma_compute_bf16<64, 67, 5, 44, false>((const uint32_t*)sHi, (const uint32_t*)sLo,
        W, bconv, xout, rowBase, sS, sQ, nullptr, nullptr);
    __syncthreads();
    if (tid < 64) { atomicAdd(&statS[tid], sS[tid]); atomicAdd(&statQ[tid], sQ[tid]); }
    tail_finalize<64>(statS, statQ, gamma, beta, sb, cnt);
}

// ---------------- Layers 1/2: BN+ReLU fused on load ----------------
template<int COUT, bool MAXMIN>
__global__ __launch_bounds__(256) void layer12_mma(
    const float* __restrict__ xin, float* __restrict__ xout,
    const float* __restrict__ W, const float* __restrict__ bconv,
    const float* __restrict__ sbin,
    float* __restrict__ statS, float* __restrict__ statQ,
    float* __restrict__ gmax, float* __restrict__ gmin,
    const float* __restrict__ gamma, const float* __restrict__ beta,
    float* __restrict__ sb, unsigned* cnt)
{
    extern __shared__ char smraw[];
    uint32_t* sHi = (uint32_t*)smraw;       // 128*36
    uint32_t* sLo = sHi + 128*36;
    float* sS  = (float*)(sLo + 128*36);    // COUT
    float* sQ  = sS + COUT;
    float* sci = sQ + COUT;                 // 128
    int tid = threadIdx.x;
    size_t rowBase = (size_t)blockIdx.x * 128;

    if (tid < 128) sci[tid] = sbin[tid];
    for (int e = tid; e < COUT; e += 256) { sS[e] = 0.0f; sQ[e] = 0.0f; }
    __syncthreads();

    const float4* src = (const float4*)(xin + rowBase*64);
    #pragma unroll
    for (int k = 0; k < 8; ++k) {
        int e4 = tid + k*256;
        float4 v = src[e4];
        int lin = e4*4; int r = lin >> 6; int c = lin & 63;
        float y0 = fmaxf(fmaf(v.x, sci[c+0], sci[64+c+0]), 0.0f);
        float y1 = fmaxf(fmaf(v.y, sci[c+1], sci[64+c+1]), 0.0f);
        float y2 = fmaxf(fmaf(v.z, sci[c+2], sci[64+c+2]), 0.0f);
        float y3 = fmaxf(fmaf(v.w, sci[c+3], sci[64+c+3]), 0.0f);
        uint2 hv, lv;
        split2(y0, y1, hv.x, lv.x);
        split2(y2, y3, hv.y, lv.y);
        int off = r*36 + (c >> 1);
        *(uint2*)(sHi + off) = hv;
        *(uint2*)(sLo + off) = lv;
    }
    __syncthreads();
    mma_compute_bf16<COUT, 64, 4, 36, MAXMIN>(sHi, sLo, W, bconv, xout, rowBase,
        sS, sQ, gmax, gmin);
    __syncthreads();
    if (tid < COUT) { atomicAdd(&statS[tid], sS[tid]); atomicAdd(&statQ[tid], sQ[tid]); }
    tail_finalize<COUT>(statS, statQ, gamma, beta, sb, cnt);
}

// ---------------- final: BN+ReLU applied to max/min over K ----------------
__global__ void final_max_kernel(const float* __restrict__ gmax, const float* __restrict__ gmin,
                                 const float* __restrict__ sb, float* __restrict__ out)
{
    int i = blockIdx.x*256 + threadIdx.x;
    int ch = i & 127;
    float sc = sb[ch], bi = sb[128 + ch];
    float v = (sc >= 0.0f) ? gmax[i] : gmin[i];
    out[XYZ_OUT + i] = fmaxf(fmaf(v, sc, bi), 0.0f);
}

// ---------------- launch ----------------
extern "C" void kernel_launch(void* const* d_in, const int* in_sizes, int n_in,
                              void* d_out, int out_size)
{
    const float* xyz    = (const float*)d_in[0];
    const float* points = (const float*)d_in[1];
    const int*   fps    = (const int*)d_in[2];
    const float* w0  = (const float*)d_in[3];
    const float* b0  = (const float*)d_in[4];
    const float* g0  = (const float*)d_in[5];
    const float* be0 = (const float*)d_in[6];
    const float* w1  = (const float*)d_in[7];
    const float* b1  = (const float*)d_in[8];
    const float* g1  = (const float*)d_in[9];
    const float* be1 = (const float*)d_in[10];
    const float* w2  = (const float*)d_in[11];
    const float* b2  = (const float*)d_in[12];
    const float* g2  = (const float*)d_in[13];
    const float* be2 = (const float*)d_in[14];
    float* out = (float*)d_out;

    float *px0, *px1, *pmx, *pmn, *pnx, *pst, *psb;
    int* pknn;
    unsigned* pcnt;
    cudaGetSymbolAddress((void**)&px0,  g_x0);
    cudaGetSymbolAddress((void**)&px1,  g_x1);
    cudaGetSymbolAddress((void**)&pmx,  g_maxv);
    cudaGetSymbolAddress((void**)&pmn,  g_minv);
    cudaGetSymbolAddress((void**)&pnx,  g_newxyz);
    cudaGetSymbolAddress((void**)&pst,  g_stats);
    cudaGetSymbolAddress((void**)&psb,  g_sb);
    cudaGetSymbolAddress((void**)&pknn, g_knn);
    cudaGetSymbolAddress((void**)&pcnt, g_cnt);

    const int SM_KNN = NN*16;                          // 65536
    const int SM0 = 128*88*2*2 + 2*64*4;               // 45568
    const int SM1 = 128*36*4*2 + (2*64 + 128)*4;       // 37888
    const int SM2 = 128*36*4*2 + (2*128 + 128)*4;      // 38400

    cudaFuncSetAttribute(knn_kernel, cudaFuncAttributeMaxDynamicSharedMemorySize, SM_KNN);
    cudaFuncSetAttribute(layer0_mma, cudaFuncAttributeMaxDynamicSharedMemorySize, SM0);
    cudaFuncSetAttribute(layer12_mma<64,false>,  cudaFuncAttributeMaxDynamicSharedMemorySize, SM1);
    cudaFuncSetAttribute(layer12_mma<128,true>, cudaFuncAttributeMaxDynamicSharedMemorySize, SM2);

    knn_kernel<<<dim3(BB, 16), 256, SM_KNN>>>(xyz, fps, pknn, pnx, out, pst);
    layer0_mma<<<ROWS/128, 256, SM0>>>(xyz, points, pknn, pnx, w0, b0, px0,
        pst, pst + 64, g0, be0, psb, pcnt);
    layer12_mma<64,false><<<ROWS/128, 256, SM1>>>(px0, px1, w1, b1, psb,
        pst + 128, pst + 192, nullptr, nullptr, g1, be1, psb + 128, pcnt + 1);
    layer12_mma<128,true><<<ROWS/128, 256, SM2>>>(px1, nullptr, w2, b2, psb + 128,
        pst + 256, pst + 384, pmx, pmn, g2, be2, psb + 256, pcnt + 2);
    final_max_kernel<<<BB*SS*128/256, 256>>>(pmx, pmn, psb + 256, out);
}